// round 14
// baseline (speedup 1.0000x reference)
#include <cuda_runtime.h>
#include <cuda_fp16.h>
#include <math.h>
#include <stdint.h>

// ContinuousRelativePositionalBias — Round 14: B fragments loop-invariant in
// registers. Each CTA owns a 64-col N-half of its tile stream; W2 fragments
// (128 regs) are ldsm'd ONCE per kernel. Steady-state main loop touches smem
// only for the 2KB bias buffer: zero ldsm, zero STS. Layer-3 partials from the
// two halves are combined by a tiny second kernel via 33.5MB device scratch.

#define ID 512
#define JD 512
#define DD 128
#define MROWS 128
#define NTHREADS 128
#define GRIDSZ 296           // 148 tile-streams x 2 N-halves
#define NTILES 8192

#define SWZ(row, chunk) ((unsigned)(row) * 256u + ((((unsigned)(chunk)) ^ ((unsigned)(row) & 7u)) << 4))

// smem byte offsets (W2 image only used during prologue ldsm)
#define OFF_W2    0          // 32KB
#define OFF_BIAS  32768      // 2 x 128 float4
#define OFF_B2    36864      // 128 floats
#define OFF_W3    37376      // 512 floats [e][o]
#define SMEM_BYTES 39424

__device__ __align__(16) uint8_t g_w2h[32768];
__device__ __align__(16) float4 g_part[2 * NTILES * MROWS];   // 33.5MB partials

__global__ void prep_w2(const float* __restrict__ W2) {
    int idx = blockIdx.x * blockDim.x + threadIdx.x;
    if (idx >= DD * DD) return;
    int n = idx >> 7, k = idx & 127;
    unsigned byte = SWZ(n, k >> 3) + (unsigned)(k & 7) * 2u;
    *(uint16_t*)(g_w2h + byte) = __half_as_ushort(__float2half_rn(W2[k * DD + n]));
}

__device__ __forceinline__ uint32_t smem_u32(const void* p) {
    uint32_t a;
    asm("{ .reg .u64 t; cvta.to.shared.u64 t, %1; cvt.u32.u64 %0, t; }" : "=r"(a) : "l"(p));
    return a;
}
__device__ __forceinline__ void ldsm_x4(uint32_t* r, uint32_t addr) {
    asm volatile("ldmatrix.sync.aligned.m8n8.x4.shared.b16 {%0,%1,%2,%3}, [%4];"
                 : "=r"(r[0]), "=r"(r[1]), "=r"(r[2]), "=r"(r[3]) : "r"(addr));
}
__device__ __forceinline__ void mma_fp16(float* c, const uint32_t* a, uint32_t b0, uint32_t b1) {
    asm volatile("mma.sync.aligned.m16n8k16.row.col.f32.f16.f16.f32 "
                 "{%0,%1,%2,%3}, {%4,%5,%6,%7}, {%8,%9}, {%0,%1,%2,%3};"
                 : "+f"(c[0]), "+f"(c[1]), "+f"(c[2]), "+f"(c[3])
                 : "r"(a[0]), "r"(a[1]), "r"(a[2]), "r"(a[3]), "r"(b0), "r"(b1));
}
__device__ __forceinline__ void mma_fp16_k8(float* c, uint32_t a0, uint32_t a1, uint32_t b0) {
    asm volatile("mma.sync.aligned.m16n8k8.row.col.f32.f16.f16.f32 "
                 "{%0,%1,%2,%3}, {%4,%5}, {%6}, {%0,%1,%2,%3};"
                 : "+f"(c[0]), "+f"(c[1]), "+f"(c[2]), "+f"(c[3])
                 : "r"(a0), "r"(a1), "r"(b0));
}
#define CP_ASYNC16(dst, src) \
    asm volatile("cp.async.cg.shared.global [%0], [%1], 16;" :: "r"(dst), "l"(src) : "memory")
#define CP_ASYNC_COMMIT() asm volatile("cp.async.commit_group;" ::: "memory")
#define CP_ASYNC_WAIT0()  asm volatile("cp.async.wait_group 0;" ::: "memory")

__device__ __forceinline__ uint32_t h2pack(float a, float b) {
    __half2 h = __floats2half2_rn(a, b);
    return *(uint32_t*)&h;
}

__device__ __forceinline__ void compute_bias(int it, float4* sB4,
                                             const float* __restrict__ grid_q,
                                             const float* __restrict__ grid_kv, int tid) {
    const int jt = it & 3;
    const int i  = (it >> 2) & (ID - 1);
    const int b  = it >> 11;
    const int j  = jt * MROWS + tid;
    const float q0 = __ldg(grid_q + i * 3 + 0);
    const float q1 = __ldg(grid_q + i * 3 + 1);
    const float q2 = __ldg(grid_q + i * 3 + 2);
    const float p0 = q0 - grid_kv[(b * JD + j) * 3 + 0];
    const float p1 = q1 - grid_kv[(b * JD + j) * 3 + 1];
    const float p2 = q2 - grid_kv[(b * JD + j) * 3 + 2];
    sB4[tid] = make_float4(copysignf(__logf(1.0f + fabsf(p0)), p0),
                           copysignf(__logf(1.0f + fabsf(p1)), p1),
                           copysignf(__logf(1.0f + fabsf(p2)), p2), 1.0f);
}

// ---------------- main persistent kernel ----------------
__global__ __launch_bounds__(NTHREADS, 2)
void crpb_kernel(const float* __restrict__ grid_q,
                 const float* __restrict__ grid_kv,
                 const float* __restrict__ W1, const float* __restrict__ b1,
                 const float* __restrict__ b2,
                 const float* __restrict__ W3)
{
    extern __shared__ __align__(1024) char smem[];
    float*  sb2   = (float*)(smem + OFF_B2);
    float*  sW3   = (float*)(smem + OFF_W3);
    float4* sBias = (float4*)(smem + OFF_BIAS);

    const int tid  = threadIdx.x;
    const int lane = tid & 31;
    const int wid  = tid >> 5;
    const int g  = lane >> 2;
    const int t4 = lane & 3;

    const int half   = blockIdx.x & 1;        // N-half: cols half*64..+63
    const int stream = blockIdx.x >> 1;       // tile stream 0..147
    const int ncol0  = half * 64;

    // ---- one-time prologue ----
    if (tid < DD) {
        sb2[tid] = b2[tid];
        reinterpret_cast<float4*>(sW3)[tid] = reinterpret_cast<const float4*>(W3)[tid];
    }
    {
        uint32_t dst = smem_u32(smem + OFF_W2) + tid * 16;
        const char* src = (const char*)g_w2h + tid * 16;
        #pragma unroll
        for (int it = 0; it < 16; ++it) CP_ASYNC16(dst + it * 2048, src + it * 2048);
        CP_ASYNC_COMMIT();
    }

    // W1_aug B-fragments (k8), persistent: 16 regs
    uint32_t W1B[16];
    #pragma unroll
    for (int ng = 0; ng < 16; ++ng) {
        const int col = ng * 8 + g;
        float v0 = 0.0f, v1 = 0.0f;
        if (t4 == 0)      { v0 = W1[col];          v1 = W1[DD + col]; }
        else if (t4 == 1) { v0 = W1[2 * DD + col]; v1 = b1[col]; }
        W1B[ng] = h2pack(v0, v1);
    }

    CP_ASYNC_WAIT0();
    __syncthreads();

    // ---- W2 fragments for THIS CTA's 64 cols: loaded ONCE, 128 regs ----
    const int brow_frag = (lane & 7) + ((lane >> 4) << 3);
    const unsigned bsel = (lane >> 3) & 1;
    const uint32_t w2b  = smem_u32(smem + OFF_W2);
    uint32_t BF[8][4][4];   // [kc][ng(16-col group)][frag]
    #pragma unroll
    for (int kc = 0; kc < 8; ++kc)
        #pragma unroll
        for (int ng = 0; ng < 4; ++ng)
            ldsm_x4(BF[kc][ng], w2b + SWZ(ncol0 + ng * 16 + brow_frag, kc * 2 + bsel));

    const int nt = (NTILES - stream + 147) / 148;
    #define TILE_AT(k) (stream + (k) * 148)

    compute_bias(TILE_AT(0), sBias, grid_q, grid_kv, tid);
    __syncthreads();

    for (int k = 0; k < nt; ++k) {
        const float4* bcur = sBias + (k & 1) * 128;
        if (k + 1 < nt)
            compute_bias(TILE_AT(k + 1), sBias + ((k + 1) & 1) * 128, grid_q, grid_kv, tid);

        // bias A-fragments (k8 layout)
        uint32_t ab[2][2];
        {
            const float4 r0 = bcur[wid * 32 + g];
            const float4 r1 = bcur[wid * 32 + 8 + g];
            const float4 r2 = bcur[wid * 32 + 16 + g];
            const float4 r3 = bcur[wid * 32 + 24 + g];
            ab[0][0] = (t4 == 0) ? h2pack(r0.x, r0.y) : (t4 == 1) ? h2pack(r0.z, r0.w) : 0u;
            ab[0][1] = (t4 == 0) ? h2pack(r1.x, r1.y) : (t4 == 1) ? h2pack(r1.z, r1.w) : 0u;
            ab[1][0] = (t4 == 0) ? h2pack(r2.x, r2.y) : (t4 == 1) ? h2pack(r2.z, r2.w) : 0u;
            ab[1][1] = (t4 == 0) ? h2pack(r3.x, r3.y) : (t4 == 1) ? h2pack(r3.z, r3.w) : 0u;
        }

        // ---- main: per kc, H1 via k8-MMA then 16 reg-resident MMAs ----
        float acc[2][8][4];
        #pragma unroll
        for (int mt = 0; mt < 2; ++mt)
            #pragma unroll
            for (int n8 = 0; n8 < 8; ++n8)
                #pragma unroll
                for (int c = 0; c < 4; ++c) acc[mt][n8][c] = 0.0f;

        #pragma unroll
        for (int kc = 0; kc < 8; ++kc) {
            uint32_t A[2][4];
            #pragma unroll
            for (int mt = 0; mt < 2; ++mt) {
                float cl[4] = {0, 0, 0, 0}, ch[4] = {0, 0, 0, 0};
                mma_fp16_k8(cl, ab[mt][0], ab[mt][1], W1B[2 * kc]);
                mma_fp16_k8(ch, ab[mt][0], ab[mt][1], W1B[2 * kc + 1]);
                A[mt][0] = h2pack(fmaxf(cl[0], 0.0f), fmaxf(cl[1], 0.0f));
                A[mt][1] = h2pack(fmaxf(cl[2], 0.0f), fmaxf(cl[3], 0.0f));
                A[mt][2] = h2pack(fmaxf(ch[0], 0.0f), fmaxf(ch[1], 0.0f));
                A[mt][3] = h2pack(fmaxf(ch[2], 0.0f), fmaxf(ch[3], 0.0f));
            }
            #pragma unroll
            for (int ng = 0; ng < 4; ++ng) {
                mma_fp16(acc[0][2 * ng],     A[0], BF[kc][ng][0], BF[kc][ng][1]);
                mma_fp16(acc[0][2 * ng + 1], A[0], BF[kc][ng][2], BF[kc][ng][3]);
                mma_fp16(acc[1][2 * ng],     A[1], BF[kc][ng][0], BF[kc][ng][1]);
                mma_fp16(acc[1][2 * ng + 1], A[1], BF[kc][ng][2], BF[kc][ng][3]);
            }
        }

        // ---- epilogue: relu(H2+b2) @ W3 over this CTA's 64 cols -> partials ----
        const int it = TILE_AT(k);
        float4* pout = g_part + (long)(half * NTILES + it) * MROWS;
        #pragma unroll
        for (int mt = 0; mt < 2; ++mt) {
            float ov[2][4] = {{0,0,0,0},{0,0,0,0}};
            #pragma unroll
            for (int n8 = 0; n8 < 8; ++n8) {
                const int e0 = ncol0 + n8 * 8 + 2 * t4;
                const float2 b2v = *(const float2*)(sb2 + e0);
                const float4 w30 = *(const float4*)(sW3 + e0 * 4);
                const float4 w31 = *(const float4*)(sW3 + (e0 + 1) * 4);
                float h00 = fmaxf(acc[mt][n8][0] + b2v.x, 0.0f);
                float h01 = fmaxf(acc[mt][n8][1] + b2v.y, 0.0f);
                float h10 = fmaxf(acc[mt][n8][2] + b2v.x, 0.0f);
                float h11 = fmaxf(acc[mt][n8][3] + b2v.y, 0.0f);
                ov[0][0] = fmaf(h00, w30.x, fmaf(h01, w31.x, ov[0][0]));
                ov[0][1] = fmaf(h00, w30.y, fmaf(h01, w31.y, ov[0][1]));
                ov[0][2] = fmaf(h00, w30.z, fmaf(h01, w31.z, ov[0][2]));
                ov[0][3] = fmaf(h00, w30.w, fmaf(h01, w31.w, ov[0][3]));
                ov[1][0] = fmaf(h10, w30.x, fmaf(h11, w31.x, ov[1][0]));
                ov[1][1] = fmaf(h10, w30.y, fmaf(h11, w31.y, ov[1][1]));
                ov[1][2] = fmaf(h10, w30.z, fmaf(h11, w31.z, ov[1][2]));
                ov[1][3] = fmaf(h10, w30.w, fmaf(h11, w31.w, ov[1][3]));
            }
            #pragma unroll
            for (int h = 0; h < 2; ++h)
                #pragma unroll
                for (int o = 0; o < 4; ++o) {
                    float v = ov[h][o];
                    v += __shfl_xor_sync(0xFFFFFFFF, v, 1);
                    v += __shfl_xor_sync(0xFFFFFFFF, v, 2);
                    ov[h][o] = v;
                }
            if (t4 == 0) {
                pout[wid * 32 + mt * 16 + g]     = make_float4(ov[0][0], ov[0][1], ov[0][2], ov[0][3]);
                pout[wid * 32 + mt * 16 + 8 + g] = make_float4(ov[1][0], ov[1][1], ov[1][2], ov[1][3]);
            }
        }
        __syncthreads();   // bias dbl-buffer handoff (the only barrier)
    }
}

// ---------------- combine: out = part0 + part1 + b3 ----------------
__global__ __launch_bounds__(256)
void combine_kernel(const float* __restrict__ b3, float* __restrict__ out)
{
    const int pt = blockIdx.x * 256 + threadIdx.x;   // 0 .. 1M-1
    const int j  = pt & (JD - 1);
    const int i  = (pt >> 9) & (ID - 1);
    const int b  = pt >> 18;
    const int tile = b * 2048 + i * 4 + (j >> 7);
    const int p    = j & 127;
    const float4 s0 = g_part[(long)tile * MROWS + p];
    const float4 s1 = g_part[(long)(NTILES + tile) * MROWS + p];
    const long base = ((long)(b * 4) * ID + i) * JD + j;
    const long os   = (long)ID * JD;
    out[base]          = s0.x + s1.x + __ldg(b3 + 0);
    out[base + os]     = s0.y + s1.y + __ldg(b3 + 1);
    out[base + 2 * os] = s0.z + s1.z + __ldg(b3 + 2);
    out[base + 3 * os] = s0.w + s1.w + __ldg(b3 + 3);
}

extern "C" void kernel_launch(void* const* d_in, const int* in_sizes, int n_in,
                              void* d_out, int out_size)
{
    const float* grid_q  = (const float*)d_in[0];
    const float* grid_kv = (const float*)d_in[1];
    const float* W1      = (const float*)d_in[2];
    const float* b1      = (const float*)d_in[3];
    const float* W2      = (const float*)d_in[4];
    const float* b2      = (const float*)d_in[5];
    const float* W3      = (const float*)d_in[6];
    const float* b3      = (const float*)d_in[7];
    float* out = (float*)d_out;

    prep_w2<<<DD * DD / 256, 256>>>(W2);

    cudaFuncSetAttribute(crpb_kernel,
                         cudaFuncAttributeMaxDynamicSharedMemorySize, SMEM_BYTES);
    crpb_kernel<<<GRIDSZ, NTHREADS, SMEM_BYTES>>>(
        grid_q, grid_kv, W1, b1, b2, W3);

    combine_kernel<<<(ID * JD * 4) / 256, 256>>>(b3, out);
}

// round 15
// speedup vs baseline: 1.2136x; 1.2136x over previous
#include <cuda_runtime.h>
#include <cuda_fp16.h>
#include <math.h>
#include <stdint.h>

// ContinuousRelativePositionalBias — Round 15: R13 workload (identical per-tile
// instruction counts) restructured for 3 CTAs/SM (regs <= 168):
//  * N-outer / K-inner main loop: acc shrinks 128 -> 16 regs; layer-3 partial
//    (ov, 16 regs) folded in per 16-col block
//  * hoisted H1 k8-MMA burst kept (A[2][8][4], 64 regs) for ILP
//  * __launch_bounds__(128,3), grid 444 -> 3 warps/SMSP

#define ID 512
#define JD 512
#define DD 128
#define MROWS 128
#define NTHREADS 128
#define GRIDSZ 444           // 3 x 148
#define NTILES 8192

#define SWZ(row, chunk) ((unsigned)(row) * 256u + ((((unsigned)(chunk)) ^ ((unsigned)(row) & 7u)) << 4))

// smem byte offsets
#define OFF_W2    0          // 32KB fp16 W2^T [n][k] swizzled
#define OFF_RED   32768      // 2 x 128 float4 (dbl-buffered)
#define OFF_BIAS  36864      // 2 x 128 float4 (dbl-buffered)
#define OFF_B2    40960      // 128 floats
#define OFF_W3    41472      // 512 floats [e][o]
#define OFF_B3    43520      // 4 floats
#define SMEM_BYTES 43536

__device__ __align__(16) uint8_t g_w2h[32768];

__global__ void prep_w2(const float* __restrict__ W2) {
    int idx = blockIdx.x * blockDim.x + threadIdx.x;
    if (idx >= DD * DD) return;
    int n = idx >> 7, k = idx & 127;
    unsigned byte = SWZ(n, k >> 3) + (unsigned)(k & 7) * 2u;
    *(uint16_t*)(g_w2h + byte) = __half_as_ushort(__float2half_rn(W2[k * DD + n]));
}

__device__ __forceinline__ uint32_t smem_u32(const void* p) {
    uint32_t a;
    asm("{ .reg .u64 t; cvta.to.shared.u64 t, %1; cvt.u32.u64 %0, t; }" : "=r"(a) : "l"(p));
    return a;
}
__device__ __forceinline__ void ldsm_x4(uint32_t* r, uint32_t addr) {
    asm volatile("ldmatrix.sync.aligned.m8n8.x4.shared.b16 {%0,%1,%2,%3}, [%4];"
                 : "=r"(r[0]), "=r"(r[1]), "=r"(r[2]), "=r"(r[3]) : "r"(addr));
}
__device__ __forceinline__ void mma_fp16(float* c, const uint32_t* a, uint32_t b0, uint32_t b1) {
    asm volatile("mma.sync.aligned.m16n8k16.row.col.f32.f16.f16.f32 "
                 "{%0,%1,%2,%3}, {%4,%5,%6,%7}, {%8,%9}, {%0,%1,%2,%3};"
                 : "+f"(c[0]), "+f"(c[1]), "+f"(c[2]), "+f"(c[3])
                 : "r"(a[0]), "r"(a[1]), "r"(a[2]), "r"(a[3]), "r"(b0), "r"(b1));
}
__device__ __forceinline__ void mma_fp16_k8(float* c, uint32_t a0, uint32_t a1, uint32_t b0) {
    asm volatile("mma.sync.aligned.m16n8k8.row.col.f32.f16.f16.f32 "
                 "{%0,%1,%2,%3}, {%4,%5}, {%6}, {%0,%1,%2,%3};"
                 : "+f"(c[0]), "+f"(c[1]), "+f"(c[2]), "+f"(c[3])
                 : "r"(a0), "r"(a1), "r"(b0));
}
#define CP_ASYNC16(dst, src) \
    asm volatile("cp.async.cg.shared.global [%0], [%1], 16;" :: "r"(dst), "l"(src) : "memory")
#define CP_ASYNC_COMMIT() asm volatile("cp.async.commit_group;" ::: "memory")
#define CP_ASYNC_WAIT0()  asm volatile("cp.async.wait_group 0;" ::: "memory")

__device__ __forceinline__ uint32_t h2pack(float a, float b) {
    __half2 h = __floats2half2_rn(a, b);
    return *(uint32_t*)&h;
}

__device__ __forceinline__ void compute_bias(int it, float4* sB4,
                                             const float* __restrict__ grid_q,
                                             const float* __restrict__ grid_kv, int tid) {
    const int jt = it & 3;
    const int i  = (it >> 2) & (ID - 1);
    const int b  = it >> 11;
    const int j  = jt * MROWS + tid;
    const float q0 = __ldg(grid_q + i * 3 + 0);
    const float q1 = __ldg(grid_q + i * 3 + 1);
    const float q2 = __ldg(grid_q + i * 3 + 2);
    const float p0 = q0 - grid_kv[(b * JD + j) * 3 + 0];
    const float p1 = q1 - grid_kv[(b * JD + j) * 3 + 1];
    const float p2 = q2 - grid_kv[(b * JD + j) * 3 + 2];
    sB4[tid] = make_float4(copysignf(__logf(1.0f + fabsf(p0)), p0),
                           copysignf(__logf(1.0f + fabsf(p1)), p1),
                           copysignf(__logf(1.0f + fabsf(p2)), p2), 1.0f);
}

// ---------------- main persistent kernel ----------------
__global__ __launch_bounds__(NTHREADS, 3)
void crpb_kernel(const float* __restrict__ grid_q,
                 const float* __restrict__ grid_kv,
                 const float* __restrict__ W1, const float* __restrict__ b1,
                 const float* __restrict__ b2,
                 const float* __restrict__ W3, const float* __restrict__ b3,
                 float* __restrict__ out)
{
    extern __shared__ __align__(1024) char smem[];
    float*  sb2   = (float*)(smem + OFF_B2);
    float*  sW3   = (float*)(smem + OFF_W3);
    float*  sb3   = (float*)(smem + OFF_B3);
    float4* sBias = (float4*)(smem + OFF_BIAS);   // 2 x 128
    float4* sRed  = (float4*)(smem + OFF_RED);    // 2 x 128

    const int tid  = threadIdx.x;
    const int lane = tid & 31;
    const int wid  = tid >> 5;
    const int g  = lane >> 2;
    const int t4 = lane & 3;

    // ---- one-time prologue ----
    if (tid < DD) {
        sb2[tid] = b2[tid];
        reinterpret_cast<float4*>(sW3)[tid] = reinterpret_cast<const float4*>(W3)[tid];
    }
    if (tid < 4) sb3[tid] = b3[tid];
    {
        uint32_t dst = smem_u32(smem + OFF_W2) + tid * 16;
        const char* src = (const char*)g_w2h + tid * 16;
        #pragma unroll
        for (int it = 0; it < 16; ++it) CP_ASYNC16(dst + it * 2048, src + it * 2048);
        CP_ASYNC_COMMIT();
    }

    // W1_aug B-fragments (k8), persistent: 16 regs
    uint32_t W1B[16];
    #pragma unroll
    for (int ng = 0; ng < 16; ++ng) {
        const int col = ng * 8 + g;
        float v0 = 0.0f, v1 = 0.0f;
        if (t4 == 0)      { v0 = W1[col];          v1 = W1[DD + col]; }
        else if (t4 == 1) { v0 = W1[2 * DD + col]; v1 = b1[col]; }
        W1B[ng] = h2pack(v0, v1);
    }

    const int nt = (NTILES - blockIdx.x + GRIDSZ - 1) / GRIDSZ;
    #define TILE_AT(k) (blockIdx.x + (k) * GRIDSZ)

    compute_bias(TILE_AT(0), sBias, grid_q, grid_kv, tid);
    CP_ASYNC_WAIT0();
    __syncthreads();

    const int brow_frag = (lane & 7) + ((lane >> 4) << 3);
    const unsigned bsel = (lane >> 3) & 1;
    const uint32_t w2b  = smem_u32(smem + OFF_W2);

    for (int k = 0; k < nt; ++k) {
        const float4* bcur = sBias + (k & 1) * 128;
        if (k + 1 < nt)
            compute_bias(TILE_AT(k + 1), sBias + ((k + 1) & 1) * 128, grid_q, grid_kv, tid);

        // bias A-fragments (k8 layout)
        uint32_t ab[2][2];
        {
            const float4 r0 = bcur[wid * 32 + g];
            const float4 r1 = bcur[wid * 32 + 8 + g];
            const float4 r2 = bcur[wid * 32 + 16 + g];
            const float4 r3 = bcur[wid * 32 + 24 + g];
            ab[0][0] = (t4 == 0) ? h2pack(r0.x, r0.y) : (t4 == 1) ? h2pack(r0.z, r0.w) : 0u;
            ab[0][1] = (t4 == 0) ? h2pack(r1.x, r1.y) : (t4 == 1) ? h2pack(r1.z, r1.w) : 0u;
            ab[1][0] = (t4 == 0) ? h2pack(r2.x, r2.y) : (t4 == 1) ? h2pack(r2.z, r2.w) : 0u;
            ab[1][1] = (t4 == 0) ? h2pack(r3.x, r3.y) : (t4 == 1) ? h2pack(r3.z, r3.w) : 0u;
        }

        // ---- H1 burst: 32 independent k8-MMAs -> all A fragments (64 regs) ----
        uint32_t A[2][8][4];
        #pragma unroll
        for (int mt = 0; mt < 2; ++mt)
            #pragma unroll
            for (int kc = 0; kc < 8; ++kc) {
                float cl[4] = {0, 0, 0, 0}, ch[4] = {0, 0, 0, 0};
                mma_fp16_k8(cl, ab[mt][0], ab[mt][1], W1B[2 * kc]);
                mma_fp16_k8(ch, ab[mt][0], ab[mt][1], W1B[2 * kc + 1]);
                A[mt][kc][0] = h2pack(fmaxf(cl[0], 0.0f), fmaxf(cl[1], 0.0f));
                A[mt][kc][1] = h2pack(fmaxf(cl[2], 0.0f), fmaxf(cl[3], 0.0f));
                A[mt][kc][2] = h2pack(fmaxf(ch[0], 0.0f), fmaxf(ch[1], 0.0f));
                A[mt][kc][3] = h2pack(fmaxf(ch[2], 0.0f), fmaxf(ch[3], 0.0f));
            }

        // ---- main: N-outer (16-col blocks), K-inner; acc 16 regs; fold into ov ----
        float ov[2][2][4];
        #pragma unroll
        for (int mt = 0; mt < 2; ++mt)
            #pragma unroll
            for (int h = 0; h < 2; ++h)
                #pragma unroll
                for (int o = 0; o < 4; ++o) ov[mt][h][o] = 0.0f;

        uint32_t Bf[2][4];
        ldsm_x4(Bf[0], w2b + SWZ(brow_frag, bsel));

        #pragma unroll
        for (int nb = 0; nb < 8; ++nb) {
            float acc[2][2][4];
            #pragma unroll
            for (int mt = 0; mt < 2; ++mt)
                #pragma unroll
                for (int n2 = 0; n2 < 2; ++n2)
                    #pragma unroll
                    for (int c = 0; c < 4; ++c) acc[mt][n2][c] = 0.0f;

            #pragma unroll
            for (int kc = 0; kc < 8; ++kc) {
                const int i = nb * 8 + kc;
                if (i < 63) {
                    const int nn = (i + 1) >> 3, kn = (i + 1) & 7;
                    ldsm_x4(Bf[(i + 1) & 1], w2b + SWZ(nn * 16 + brow_frag, kn * 2 + bsel));
                }
                const uint32_t* B = Bf[i & 1];
                mma_fp16(acc[0][0], A[0][kc], B[0], B[1]);
                mma_fp16(acc[0][1], A[0][kc], B[2], B[3]);
                mma_fp16(acc[1][0], A[1][kc], B[0], B[1]);
                mma_fp16(acc[1][1], A[1][kc], B[2], B[3]);
            }

            // fold this 16-col block into layer-3 partials
            #pragma unroll
            for (int n2 = 0; n2 < 2; ++n2) {
                const int e0 = nb * 16 + n2 * 8 + 2 * t4;
                const float2 b2v = *(const float2*)(sb2 + e0);
                const float4 w30 = *(const float4*)(sW3 + e0 * 4);
                const float4 w31 = *(const float4*)(sW3 + (e0 + 1) * 4);
                #pragma unroll
                for (int mt = 0; mt < 2; ++mt) {
                    float h00 = fmaxf(acc[mt][n2][0] + b2v.x, 0.0f);
                    float h01 = fmaxf(acc[mt][n2][1] + b2v.y, 0.0f);
                    float h10 = fmaxf(acc[mt][n2][2] + b2v.x, 0.0f);
                    float h11 = fmaxf(acc[mt][n2][3] + b2v.y, 0.0f);
                    ov[mt][0][0] = fmaf(h00, w30.x, fmaf(h01, w31.x, ov[mt][0][0]));
                    ov[mt][0][1] = fmaf(h00, w30.y, fmaf(h01, w31.y, ov[mt][0][1]));
                    ov[mt][0][2] = fmaf(h00, w30.z, fmaf(h01, w31.z, ov[mt][0][2]));
                    ov[mt][0][3] = fmaf(h00, w30.w, fmaf(h01, w31.w, ov[mt][0][3]));
                    ov[mt][1][0] = fmaf(h10, w30.x, fmaf(h11, w31.x, ov[mt][1][0]));
                    ov[mt][1][1] = fmaf(h10, w30.y, fmaf(h11, w31.y, ov[mt][1][1]));
                    ov[mt][1][2] = fmaf(h10, w30.z, fmaf(h11, w31.z, ov[mt][1][2]));
                    ov[mt][1][3] = fmaf(h10, w30.w, fmaf(h11, w31.w, ov[mt][1][3]));
                }
            }
        }

        // ---- reduce + store ----
        float4* redc = sRed + (k & 1) * 128;
        #pragma unroll
        for (int mt = 0; mt < 2; ++mt) {
            #pragma unroll
            for (int h = 0; h < 2; ++h)
                #pragma unroll
                for (int o = 0; o < 4; ++o) {
                    float v = ov[mt][h][o];
                    v += __shfl_xor_sync(0xFFFFFFFF, v, 1);
                    v += __shfl_xor_sync(0xFFFFFFFF, v, 2);
                    ov[mt][h][o] = v;
                }
            if (t4 == 0) {
                redc[wid * 32 + mt * 16 + g]     = make_float4(ov[mt][0][0], ov[mt][0][1], ov[mt][0][2], ov[mt][0][3]);
                redc[wid * 32 + mt * 16 + 8 + g] = make_float4(ov[mt][1][0], ov[mt][1][1], ov[mt][1][2], ov[mt][1][3]);
            }
        }
        __syncthreads();   // single barrier per iteration

        {
            const float4 r = redc[tid];
            const int it = TILE_AT(k);
            const int jt = it & 3;
            const int i  = (it >> 2) & (ID - 1);
            const int b  = it >> 11;
            const long base = ((long)(b * 4) * ID + i) * JD + jt * MROWS + tid;
            const long os   = (long)ID * JD;
            out[base]          = r.x + sb3[0];
            out[base + os]     = r.y + sb3[1];
            out[base + 2 * os] = r.z + sb3[2];
            out[base + 3 * os] = r.w + sb3[3];
        }
    }
}

extern "C" void kernel_launch(void* const* d_in, const int* in_sizes, int n_in,
                              void* d_out, int out_size)
{
    const float* grid_q  = (const float*)d_in[0];
    const float* grid_kv = (const float*)d_in[1];
    const float* W1      = (const float*)d_in[2];
    const float* b1      = (const float*)d_in[3];
    const float* W2      = (const float*)d_in[4];
    const float* b2      = (const float*)d_in[5];
    const float* W3      = (const float*)d_in[6];
    const float* b3      = (const float*)d_in[7];
    float* out = (float*)d_out;

    prep_w2<<<DD * DD / 256, 256>>>(W2);

    cudaFuncSetAttribute(crpb_kernel,
                         cudaFuncAttributeMaxDynamicSharedMemorySize, SMEM_BYTES);
    crpb_kernel<<<GRIDSZ, NTHREADS, SMEM_BYTES>>>(
        grid_q, grid_kv, W1, b1, b2, W3, b3, out);
}

// round 16
// speedup vs baseline: 1.3480x; 1.1107x over previous
#include <cuda_runtime.h>
#include <cuda_fp16.h>
#include <math.h>
#include <stdint.h>

// ContinuousRelativePositionalBias — Round 16: ALL THREE layers on tensor cores.
//  L1: bias_pad @ W1_aug   via k8 MMA  (C-frag == A-frag, R11)
//  L2: H1 @ W2             via k16 MMA (B from smem, reg A)
//  L3: relu(H2+b2) @ W3^T  via k16 MMA (acc C-frag == A-frag again; W3 padded
//      4->8 cols; K fully contracted in-MMA => NO quad shuffles, no FFMA fold)
// 3 CTAs/SM (regs<=168), N-outer/K-inner main loop, 1 barrier/iter.

#define ID 512
#define JD 512
#define DD 128
#define MROWS 128
#define NTHREADS 128
#define GRIDSZ 444           // 3 x 148
#define NTILES 8192

#define SWZ(row, chunk) ((unsigned)(row) * 256u + ((((unsigned)(chunk)) ^ ((unsigned)(row) & 7u)) << 4))

// smem byte offsets
#define OFF_W2    0          // 32KB fp16 W2^T [n][k] swizzled
#define OFF_W3T   32768      // 4KB: 16 rows (o, padded) x 128 k (e) fp16, swizzled
#define OFF_RED   36864      // 2 x 128 float4 (dbl-buffered)
#define OFF_BIAS  40960      // 2 x 128 float4 (dbl-buffered)
#define OFF_B2    45056      // 128 floats
#define OFF_B3    45568      // 4 floats
#define SMEM_BYTES 45584

__device__ __align__(16) uint8_t g_w2h[32768];

__global__ void prep_w2(const float* __restrict__ W2) {
    int idx = blockIdx.x * blockDim.x + threadIdx.x;
    if (idx >= DD * DD) return;
    int n = idx >> 7, k = idx & 127;
    unsigned byte = SWZ(n, k >> 3) + (unsigned)(k & 7) * 2u;
    *(uint16_t*)(g_w2h + byte) = __half_as_ushort(__float2half_rn(W2[k * DD + n]));
}

__device__ __forceinline__ uint32_t smem_u32(const void* p) {
    uint32_t a;
    asm("{ .reg .u64 t; cvta.to.shared.u64 t, %1; cvt.u32.u64 %0, t; }" : "=r"(a) : "l"(p));
    return a;
}
__device__ __forceinline__ void ldsm_x4(uint32_t* r, uint32_t addr) {
    asm volatile("ldmatrix.sync.aligned.m8n8.x4.shared.b16 {%0,%1,%2,%3}, [%4];"
                 : "=r"(r[0]), "=r"(r[1]), "=r"(r[2]), "=r"(r[3]) : "r"(addr));
}
__device__ __forceinline__ void mma_fp16(float* c, const uint32_t* a, uint32_t b0, uint32_t b1) {
    asm volatile("mma.sync.aligned.m16n8k16.row.col.f32.f16.f16.f32 "
                 "{%0,%1,%2,%3}, {%4,%5,%6,%7}, {%8,%9}, {%0,%1,%2,%3};"
                 : "+f"(c[0]), "+f"(c[1]), "+f"(c[2]), "+f"(c[3])
                 : "r"(a[0]), "r"(a[1]), "r"(a[2]), "r"(a[3]), "r"(b0), "r"(b1));
}
__device__ __forceinline__ void mma_fp16_k8(float* c, uint32_t a0, uint32_t a1, uint32_t b0) {
    asm volatile("mma.sync.aligned.m16n8k8.row.col.f32.f16.f16.f32 "
                 "{%0,%1,%2,%3}, {%4,%5}, {%6}, {%0,%1,%2,%3};"
                 : "+f"(c[0]), "+f"(c[1]), "+f"(c[2]), "+f"(c[3])
                 : "r"(a0), "r"(a1), "r"(b0));
}
#define CP_ASYNC16(dst, src) \
    asm volatile("cp.async.cg.shared.global [%0], [%1], 16;" :: "r"(dst), "l"(src) : "memory")
#define CP_ASYNC_COMMIT() asm volatile("cp.async.commit_group;" ::: "memory")
#define CP_ASYNC_WAIT0()  asm volatile("cp.async.wait_group 0;" ::: "memory")

__device__ __forceinline__ uint32_t h2pack(float a, float b) {
    __half2 h = __floats2half2_rn(a, b);
    return *(uint32_t*)&h;
}

__device__ __forceinline__ void compute_bias(int it, float4* sB4,
                                             const float* __restrict__ grid_q,
                                             const float* __restrict__ grid_kv, int tid) {
    const int jt = it & 3;
    const int i  = (it >> 2) & (ID - 1);
    const int b  = it >> 11;
    const int j  = jt * MROWS + tid;
    const float q0 = __ldg(grid_q + i * 3 + 0);
    const float q1 = __ldg(grid_q + i * 3 + 1);
    const float q2 = __ldg(grid_q + i * 3 + 2);
    const float p0 = q0 - grid_kv[(b * JD + j) * 3 + 0];
    const float p1 = q1 - grid_kv[(b * JD + j) * 3 + 1];
    const float p2 = q2 - grid_kv[(b * JD + j) * 3 + 2];
    sB4[tid] = make_float4(copysignf(__logf(1.0f + fabsf(p0)), p0),
                           copysignf(__logf(1.0f + fabsf(p1)), p1),
                           copysignf(__logf(1.0f + fabsf(p2)), p2), 1.0f);
}

// ---------------- main persistent kernel ----------------
__global__ __launch_bounds__(NTHREADS, 3)
void crpb_kernel(const float* __restrict__ grid_q,
                 const float* __restrict__ grid_kv,
                 const float* __restrict__ W1, const float* __restrict__ b1,
                 const float* __restrict__ b2,
                 const float* __restrict__ W3, const float* __restrict__ b3,
                 float* __restrict__ out)
{
    extern __shared__ __align__(1024) char smem[];
    float*  sb2   = (float*)(smem + OFF_B2);
    float*  sb3   = (float*)(smem + OFF_B3);
    float4* sBias = (float4*)(smem + OFF_BIAS);   // 2 x 128
    float4* sRed  = (float4*)(smem + OFF_RED);    // 2 x 128

    const int tid  = threadIdx.x;
    const int lane = tid & 31;
    const int wid  = tid >> 5;
    const int g  = lane >> 2;
    const int t4 = lane & 3;

    // ---- one-time prologue ----
    if (tid < DD) {
        sb2[tid] = b2[tid];
        // W3T image: 16 rows (o, rows 4..15 zero) x 128 cols (e), swizzled fp16
        const int e = tid;
        #pragma unroll
        for (int n = 0; n < 16; ++n) {
            unsigned byte = SWZ(n, e >> 3) + (unsigned)(e & 7) * 2u;
            float v = (n < 4) ? W3[e * 4 + n] : 0.0f;
            *(uint16_t*)(smem + OFF_W3T + byte) = __half_as_ushort(__float2half_rn(v));
        }
    }
    if (tid < 4) sb3[tid] = b3[tid];
    {
        uint32_t dst = smem_u32(smem + OFF_W2) + tid * 16;
        const char* src = (const char*)g_w2h + tid * 16;
        #pragma unroll
        for (int it = 0; it < 16; ++it) CP_ASYNC16(dst + it * 2048, src + it * 2048);
        CP_ASYNC_COMMIT();
    }

    // W1_aug B-fragments (k8), persistent: 16 regs
    uint32_t W1B[16];
    #pragma unroll
    for (int ng = 0; ng < 16; ++ng) {
        const int col = ng * 8 + g;
        float v0 = 0.0f, v1 = 0.0f;
        if (t4 == 0)      { v0 = W1[col];          v1 = W1[DD + col]; }
        else if (t4 == 1) { v0 = W1[2 * DD + col]; v1 = b1[col]; }
        W1B[ng] = h2pack(v0, v1);
    }

    const int nt = (NTILES - blockIdx.x + GRIDSZ - 1) / GRIDSZ;
    #define TILE_AT(k) (blockIdx.x + (k) * GRIDSZ)

    compute_bias(TILE_AT(0), sBias, grid_q, grid_kv, tid);
    CP_ASYNC_WAIT0();
    __syncthreads();

    const int brow_frag = (lane & 7) + ((lane >> 4) << 3);
    const unsigned bsel = (lane >> 3) & 1;
    const uint32_t w2b  = smem_u32(smem + OFF_W2);
    const uint32_t w3b  = smem_u32(smem + OFF_W3T);

    for (int k = 0; k < nt; ++k) {
        const float4* bcur = sBias + (k & 1) * 128;
        if (k + 1 < nt)
            compute_bias(TILE_AT(k + 1), sBias + ((k + 1) & 1) * 128, grid_q, grid_kv, tid);

        // bias A-fragments (k8 layout)
        uint32_t ab[2][2];
        {
            const float4 r0 = bcur[wid * 32 + g];
            const float4 r1 = bcur[wid * 32 + 8 + g];
            const float4 r2 = bcur[wid * 32 + 16 + g];
            const float4 r3 = bcur[wid * 32 + 24 + g];
            ab[0][0] = (t4 == 0) ? h2pack(r0.x, r0.y) : (t4 == 1) ? h2pack(r0.z, r0.w) : 0u;
            ab[0][1] = (t4 == 0) ? h2pack(r1.x, r1.y) : (t4 == 1) ? h2pack(r1.z, r1.w) : 0u;
            ab[1][0] = (t4 == 0) ? h2pack(r2.x, r2.y) : (t4 == 1) ? h2pack(r2.z, r2.w) : 0u;
            ab[1][1] = (t4 == 0) ? h2pack(r3.x, r3.y) : (t4 == 1) ? h2pack(r3.z, r3.w) : 0u;
        }

        // ---- L1 burst: 32 independent k8-MMAs -> all A fragments (64 regs) ----
        uint32_t A[2][8][4];
        #pragma unroll
        for (int mt = 0; mt < 2; ++mt)
            #pragma unroll
            for (int kc = 0; kc < 8; ++kc) {
                float cl[4] = {0, 0, 0, 0}, ch[4] = {0, 0, 0, 0};
                mma_fp16_k8(cl, ab[mt][0], ab[mt][1], W1B[2 * kc]);
                mma_fp16_k8(ch, ab[mt][0], ab[mt][1], W1B[2 * kc + 1]);
                A[mt][kc][0] = h2pack(fmaxf(cl[0], 0.0f), fmaxf(cl[1], 0.0f));
                A[mt][kc][1] = h2pack(fmaxf(cl[2], 0.0f), fmaxf(cl[3], 0.0f));
                A[mt][kc][2] = h2pack(fmaxf(ch[0], 0.0f), fmaxf(ch[1], 0.0f));
                A[mt][kc][3] = h2pack(fmaxf(ch[2], 0.0f), fmaxf(ch[3], 0.0f));
            }

        // ---- L2 (N-outer, K-inner) + L3 fold-by-MMA ----
        float ovC[2][4];                    // layer-3 accumulators (fp32, via MMA)
        #pragma unroll
        for (int mt = 0; mt < 2; ++mt)
            #pragma unroll
            for (int c = 0; c < 4; ++c) ovC[mt][c] = 0.0f;

        uint32_t Bf[2][4];
        ldsm_x4(Bf[0], w2b + SWZ(brow_frag, bsel));

        #pragma unroll
        for (int nb = 0; nb < 8; ++nb) {
            float acc[2][2][4];
            #pragma unroll
            for (int mt = 0; mt < 2; ++mt)
                #pragma unroll
                for (int n2 = 0; n2 < 2; ++n2)
                    #pragma unroll
                    for (int c = 0; c < 4; ++c) acc[mt][n2][c] = 0.0f;

            #pragma unroll
            for (int kc = 0; kc < 8; ++kc) {
                const int i = nb * 8 + kc;
                if (i < 63) {
                    const int nn = (i + 1) >> 3, kn = (i + 1) & 7;
                    ldsm_x4(Bf[(i + 1) & 1], w2b + SWZ(nn * 16 + brow_frag, kn * 2 + bsel));
                }
                const uint32_t* B = Bf[i & 1];
                mma_fp16(acc[0][0], A[0][kc], B[0], B[1]);
                mma_fp16(acc[0][1], A[0][kc], B[2], B[3]);
                mma_fp16(acc[1][0], A[1][kc], B[0], B[1]);
                mma_fp16(acc[1][1], A[1][kc], B[2], B[3]);
            }

            // L3 fold: relu(acc + b2) -> A' frags -> 2 MMAs vs W3T (K = 16 cols)
            uint32_t W3f[4];
            ldsm_x4(W3f, w3b + SWZ(brow_frag, nb * 2 + bsel));
            const int e0 = nb * 16 + 2 * t4;
            const float2 b2a = *(const float2*)(sb2 + e0);
            const float2 b2b = *(const float2*)(sb2 + e0 + 8);
            #pragma unroll
            for (int mt = 0; mt < 2; ++mt) {
                uint32_t Ap[4];
                Ap[0] = h2pack(fmaxf(acc[mt][0][0] + b2a.x, 0.0f), fmaxf(acc[mt][0][1] + b2a.y, 0.0f));
                Ap[1] = h2pack(fmaxf(acc[mt][0][2] + b2a.x, 0.0f), fmaxf(acc[mt][0][3] + b2a.y, 0.0f));
                Ap[2] = h2pack(fmaxf(acc[mt][1][0] + b2b.x, 0.0f), fmaxf(acc[mt][1][1] + b2b.y, 0.0f));
                Ap[3] = h2pack(fmaxf(acc[mt][1][2] + b2b.x, 0.0f), fmaxf(acc[mt][1][3] + b2b.y, 0.0f));
                mma_fp16(ovC[mt], Ap, W3f[0], W3f[1]);
            }
        }

        // ---- store: ovC cols = output o (lanes t4<2 hold o0..o3), no shuffles ----
        float4* redc = sRed + (k & 1) * 128;
        float2* redc2 = (float2*)redc;
        if (t4 < 2) {
            #pragma unroll
            for (int mt = 0; mt < 2; ++mt) {
                redc2[(wid * 32 + mt * 16 + g) * 2 + t4]     = make_float2(ovC[mt][0], ovC[mt][1]);
                redc2[(wid * 32 + mt * 16 + 8 + g) * 2 + t4] = make_float2(ovC[mt][2], ovC[mt][3]);
            }
        }
        __syncthreads();   // single barrier per iteration

        {
            const float4 r = redc[tid];
            const int it = TILE_AT(k);
            const int jt = it & 3;
            const int i  = (it >> 2) & (ID - 1);
            const int b  = it >> 11;
            const long base = ((long)(b * 4) * ID + i) * JD + jt * MROWS + tid;
            const long os   = (long)ID * JD;
            out[base]          = r.x + sb3[0];
            out[base + os]     = r.y + sb3[1];
            out[base + 2 * os] = r.z + sb3[2];
            out[base + 3 * os] = r.w + sb3[3];
        }
    }
}

extern "C" void kernel_launch(void* const* d_in, const int* in_sizes, int n_in,
                              void* d_out, int out_size)
{
    const float* grid_q  = (const float*)d_in[0];
    const float* grid_kv = (const float*)d_in[1];
    const float* W1      = (const float*)d_in[2];
    const float* b1      = (const float*)d_in[3];
    const float* W2      = (const float*)d_in[4];
    const float* b2      = (const float*)d_in[5];
    const float* W3      = (const float*)d_in[6];
    const float* b3      = (const float*)d_in[7];
    float* out = (float*)d_out;

    prep_w2<<<DD * DD / 256, 256>>>(W2);

    cudaFuncSetAttribute(crpb_kernel,
                         cudaFuncAttributeMaxDynamicSharedMemorySize, SMEM_BYTES);
    crpb_kernel<<<GRIDSZ, NTHREADS, SMEM_BYTES>>>(
        grid_q, grid_kv, W1, b1, b2, W3, b3, out);
}